// round 8
// baseline (speedup 1.0000x reference)
#include <cuda_runtime.h>
#include <math.h>

// EMD approxmatch (Fan et al.) on GB300 — round 8.
// Sparse sweeps (s0-s4): column-split (CS=4) blocks + chunk-mask pruning +
// atomic partial-sum reduction + tiny epilogue kernels (kills straggler blocks).
// Dense sweeps (s5-s8) and exact level-0 unchanged (at MUFU floor). B=4, N=4096.

#define EMD_EPS 1e-9f
#define NB 4
#define MAXBN (NB * 4096)
#define TILE 1024      // dense tiles
#define TS   256       // sparse tiles
#define RPB 16         // rows per block: 4 warps x 4 rows
#define CS  4          // column-split factor for sparse sweeps

typedef unsigned long long u64;

__device__ float4 g_p1[MAXBN];   // sorted (x,y,z,|p|^2) xyz1
__device__ float4 g_p2[MAXBN];   // sorted (x,y,z,|p|^2) xyz2
__device__ float  g_rL[MAXBN];
__device__ float  g_rR[MAXBN];
__device__ float  g_l2R[MAXBN];  // log2(remainR)
__device__ float  g_lgL[MAXBN];  // log2(ratioL)  (raw ratioL during level-0 sweep)
__device__ float  g_lgR[MAXBN];  // log2(ratioR)  (raw ratioR during level-0 sweep)
__device__ float  g_sum[MAXBN];  // split-K partial-sum accumulator (zeroed after each use)
__device__ float  g_cost;
__device__ float4 g_cb[2][NB * 64 * 2];  // 64-pt chunk bboxes

__device__ __forceinline__ float ex2f(float x) {
    float y; asm("ex2.approx.ftz.f32 %0, %1;" : "=f"(y) : "f"(x)); return y;
}
__device__ __forceinline__ float lg2f(float x) {
    float y; asm("lg2.approx.ftz.f32 %0, %1;" : "=f"(y) : "f"(x)); return y;
}
__device__ __forceinline__ float sqrtf_apx(float x) {
    float y; asm("sqrt.approx.ftz.f32 %0, %1;" : "=f"(y) : "f"(x)); return y;
}
__device__ __forceinline__ u64 pk2(float a, float b) {
    u64 r; asm("mov.b64 %0, {%1, %2};" : "=l"(r) : "f"(a), "f"(b)); return r;
}
__device__ __forceinline__ void upk2(float& a, float& b, u64 v) {
    asm("mov.b64 {%0, %1}, %2;" : "=f"(a), "=f"(b) : "l"(v));
}
__device__ __forceinline__ u64 f2fma(u64 a, u64 b, u64 c) {
    u64 d; asm("fma.rn.f32x2 %0, %1, %2, %3;" : "=l"(d) : "l"(a), "l"(b), "l"(c)); return d;
}
__device__ __forceinline__ u64 f2add(u64 a, u64 b) {
    u64 d; asm("add.rn.f32x2 %0, %1, %2;" : "=l"(d) : "l"(a), "l"(b)); return d;
}

#define UF_TH (-125.0f)

__device__ __forceinline__ unsigned mort1(unsigned v) {
    return (v & 1u) | ((v & 2u) << 2) | ((v & 4u) << 4);
}

__device__ __forceinline__ bool chunk_skip(const float4* CB, int ci,
                                           float wlx, float wly, float wlz,
                                           float whx, float why, float whz, float cut2) {
    float4 clo = __ldg(&CB[ci * 2]);
    float4 chi = __ldg(&CB[ci * 2 + 1]);
    float gx = fmaxf(0.0f, fmaxf(clo.x - whx, wlx - chi.x));
    float gy = fmaxf(0.0f, fmaxf(clo.y - why, wly - chi.y));
    float gz = fmaxf(0.0f, fmaxf(clo.z - whz, wlz - chi.z));
    return gx * gx + gy * gy + gz * gz > cut2;
}

// Counting sort by Morton cell id (8^3 cells over [-4,4]^3). grid (B,2), block 512.
__global__ void sort_kernel(const float* __restrict__ x1, const float* __restrict__ x2,
                            float multiL, float multiR, int N) {
    __shared__ unsigned hist[512];
    __shared__ unsigned scan[512];
    __shared__ unsigned offs[512];
    const int b = blockIdx.x, side = blockIdx.y, t = threadIdx.x;
    const float* px = (side ? x2 : x1) + (size_t)b * 3 * N;
    hist[t] = 0;
    __syncthreads();
    for (int i = t; i < N; i += 512) {
        float a = px[i], c = px[i + N], d = px[i + 2 * N];
        unsigned cx = (unsigned)min(7, max(0, (int)floorf(a + 4.0f)));
        unsigned cy = (unsigned)min(7, max(0, (int)floorf(c + 4.0f)));
        unsigned cz = (unsigned)min(7, max(0, (int)floorf(d + 4.0f)));
        unsigned cell = mort1(cx) | (mort1(cy) << 1) | (mort1(cz) << 2);
        atomicAdd(&hist[cell], 1u);
    }
    __syncthreads();
    scan[t] = hist[t];
    __syncthreads();
    for (int o = 1; o < 512; o <<= 1) {
        unsigned add = (t >= o) ? scan[t - o] : 0u;
        __syncthreads();
        scan[t] += add;
        __syncthreads();
    }
    offs[t] = scan[t] - hist[t];
    __syncthreads();
    for (int i = t; i < N; i += 512) {
        float a = px[i], c = px[i + N], d = px[i + 2 * N];
        unsigned cx = (unsigned)min(7, max(0, (int)floorf(a + 4.0f)));
        unsigned cy = (unsigned)min(7, max(0, (int)floorf(c + 4.0f)));
        unsigned cz = (unsigned)min(7, max(0, (int)floorf(d + 4.0f)));
        unsigned cell = mort1(cx) | (mort1(cy) << 1) | (mort1(cz) << 2);
        unsigned pos = atomicAdd(&offs[cell], 1u);
        int idx = b * N + (int)pos;
        float4 v = make_float4(a, c, d, a * a + c * c + d * d);
        if (side == 0) { g_p1[idx] = v; g_rL[idx] = multiL; g_sum[idx] = 0.0f; }
        else           { g_p2[idx] = v; g_rR[idx] = multiR; g_l2R[idx] = lg2f(multiR); }
    }
    if (b == 0 && side == 0 && t == 0) g_cost = 0.0f;
}

// Chunk (64-pt) bboxes. grid (B,2), block 512.
__global__ void bbox_kernel(int N) {
    const int b = blockIdx.x, side = blockIdx.y, t = threadIdx.x;
    const int warp = t >> 5, lane = t & 31;
    const float4* P = side ? g_p2 : g_p1;
    float4* CB = g_cb[side];
    for (int c = warp; c < 64; c += 16) {
        int j = b * N + c * 64 + lane;
        float4 p0 = P[j], p1 = P[j + 32];
        float lx = fminf(p0.x, p1.x), hx = fmaxf(p0.x, p1.x);
        float ly = fminf(p0.y, p1.y), hy = fmaxf(p0.y, p1.y);
        float lz = fminf(p0.z, p1.z), hz = fmaxf(p0.z, p1.z);
#pragma unroll
        for (int o = 16; o; o >>= 1) {
            lx = fminf(lx, __shfl_xor_sync(0xffffffffu, lx, o));
            hx = fmaxf(hx, __shfl_xor_sync(0xffffffffu, hx, o));
            ly = fminf(ly, __shfl_xor_sync(0xffffffffu, ly, o));
            hy = fmaxf(hy, __shfl_xor_sync(0xffffffffu, hy, o));
            lz = fminf(lz, __shfl_xor_sync(0xffffffffu, lz, o));
            hz = fmaxf(hz, __shfl_xor_sync(0xffffffffu, hz, o));
        }
        if (lane == 0) {
            CB[(b * 64 + c) * 2]     = make_float4(lx, ly, lz, 0.0f);
            CB[(b * 64 + c) * 2 + 1] = make_float4(hx, hy, hz, 0.0f);
        }
    }
}

// ---------------- epilogue helper (dense kernels keep inline epilogues) ----------------
__device__ __forceinline__ void epi12(int MODE, int idx, float a) {
    if (MODE == 1) {
        g_lgL[idx] = lg2f(g_rL[idx] / (EMD_EPS + a));
    } else {
        float rr   = g_rR[idx];
        float sumr = rr * a;
        float cons = fminf(rr / (sumr + EMD_EPS), 1.0f);
        float nrr  = fmaxf(0.0f, rr - sumr);
        g_lgR[idx] = lg2f(cons * rr);
        g_rR[idx]  = nrr;
        g_l2R[idx] = lg2f(nrr);
    }
}

// ---------------- SPARSE sum kernels (column-split, atomic partial sums) ----------------
// grid (N/RPB, B, CS). Each block scans columns [z*N/CS, (z+1)*N/CS).
// MODE 1: rows=x1, cols=x2, fold=g_l2R.  MODE 2: rows=x2, cols=x1, fold=g_lgL.
template <int MODE>
__global__ void __launch_bounds__(128, 8) sparse12_sum(float klg, float cut2, int N) {
    __shared__ ulonglong2 s_xy[TS / 2];
    __shared__ ulonglong2 s_zf[TS / 2];
    const int b = blockIdx.y, base = b * N;
    const int t = threadIdx.x, warp = t >> 5, lane = t & 31;
    const int r0 = blockIdx.x * RPB + warp * 4;
    const int c0 = blockIdx.z * (N / CS), c1 = c0 + N / CS;

    const float4* P    = (MODE == 1) ? g_p1 : g_p2;
    const float4* Q    = (MODE == 1) ? g_p2 : g_p1;
    const float4* CB   = (MODE == 1) ? g_cb[1] : g_cb[0];
    const float*  FOLD = (MODE == 1) ? g_l2R : g_lgL;

    u64 rx[4], ry[4], rz[4], rw[4], acc[4];
    u64 wm;
    {
        float4 A[4];
#pragma unroll
        for (int r = 0; r < 4; r++) A[r] = P[base + r0 + r];
#pragma unroll
        for (int r = 0; r < 4; r++) {
            float kx = klg * -2.0f * A[r].x, ky = klg * -2.0f * A[r].y, kz = klg * -2.0f * A[r].z;
            float kw = klg * A[r].w;
            rx[r] = pk2(kx, kx); ry[r] = pk2(ky, ky); rz[r] = pk2(kz, kz); rw[r] = pk2(kw, kw);
            acc[r] = 0ull;
        }
        float wlx = fminf(fminf(A[0].x, A[1].x), fminf(A[2].x, A[3].x));
        float whx = fmaxf(fmaxf(A[0].x, A[1].x), fmaxf(A[2].x, A[3].x));
        float wly = fminf(fminf(A[0].y, A[1].y), fminf(A[2].y, A[3].y));
        float why = fmaxf(fmaxf(A[0].y, A[1].y), fmaxf(A[2].y, A[3].y));
        float wlz = fminf(fminf(A[0].z, A[1].z), fminf(A[2].z, A[3].z));
        float whz = fmaxf(fmaxf(A[0].z, A[1].z), fmaxf(A[2].z, A[3].z));
        bool k0 = chunk_skip(CB, b * 64 + lane,      wlx, wly, wlz, whx, why, whz, cut2);
        bool k1 = chunk_skip(CB, b * 64 + lane + 32, wlx, wly, wlz, whx, why, whz, cut2);
        wm = ((u64)__ballot_sync(0xffffffffu, k1) << 32) |
             (u64)__ballot_sync(0xffffffffu, k0);
    }

    for (int c = c0; c < c1; c += TS) {
        const int tb = c >> 6;   // first chunk of this tile (4 chunks/tile)
        if (((wm >> tb) & 0xFull) == 0xFull) {   // warp-local tile test feeds block vote
            if (__syncthreads_and(1)) continue;  // all warps dead -> skip fill+math
        } else {
            __syncthreads_and(0);
        }
        {
            int j = base + c + 2 * t;
            float4 q0 = Q[j], q1 = Q[j + 1];
            float2 fo = *(const float2*)&FOLD[j];
            float f0 = fmaf(klg, q0.w, fo.x);
            float f1 = fmaf(klg, q1.w, fo.y);
            ulonglong2 xy; xy.x = pk2(q0.x, q1.x); xy.y = pk2(q0.y, q1.y);
            ulonglong2 zf; zf.x = pk2(q0.z, q1.z); zf.y = pk2(f0, f1);
            s_xy[t] = xy; s_zf[t] = zf;
        }
        __syncthreads();
#pragma unroll
        for (int it = 0; it < TS / 64; it++) {
            if ((wm >> (tb + it)) & 1ull) continue;
            int p = it * 32 + lane;
            ulonglong2 xy = s_xy[p];
            ulonglong2 zf = s_zf[p];
            u64 a0 = f2fma(rz[0], zf.x, f2fma(ry[0], xy.y, f2fma(rx[0], xy.x, f2add(zf.y, rw[0]))));
            u64 a1 = f2fma(rz[1], zf.x, f2fma(ry[1], xy.y, f2fma(rx[1], xy.x, f2add(zf.y, rw[1]))));
            u64 a2 = f2fma(rz[2], zf.x, f2fma(ry[2], xy.y, f2fma(rx[2], xy.x, f2add(zf.y, rw[2]))));
            u64 a3 = f2fma(rz[3], zf.x, f2fma(ry[3], xy.y, f2fma(rx[3], xy.x, f2add(zf.y, rw[3]))));
            float e0, e1, e2, e3, e4, e5, e6, e7;
            upk2(e0, e1, a0); upk2(e2, e3, a1); upk2(e4, e5, a2); upk2(e6, e7, a3);
            float m0 = fmaxf(fmaxf(e0, e1), fmaxf(e2, e3));
            float m1 = fmaxf(fmaxf(e4, e5), fmaxf(e6, e7));
            if (__all_sync(0xffffffffu, fmaxf(m0, m1) < UF_TH)) continue;
            acc[0] = f2add(acc[0], pk2(ex2f(e0), ex2f(e1)));
            acc[1] = f2add(acc[1], pk2(ex2f(e2), ex2f(e3)));
            acc[2] = f2add(acc[2], pk2(ex2f(e4), ex2f(e5)));
            acc[3] = f2add(acc[3], pk2(ex2f(e6), ex2f(e7)));
        }
        __syncthreads();
    }

#pragma unroll
    for (int off = 16; off; off >>= 1) {
#pragma unroll
        for (int r = 0; r < 4; r++)
            acc[r] = f2add(acc[r], __shfl_down_sync(0xffffffffu, acc[r], off));
    }
    if (lane == 0) {
#pragma unroll
        for (int r = 0; r < 4; r++) {
            float lo, hi; upk2(lo, hi, acc[r]);
            float a = lo + hi;
            if (a != 0.0f) atomicAdd(&g_sum[base + r0 + r], a);
        }
    }
}

__global__ void __launch_bounds__(128, 8) sparse3_sum(float klg, float cut2, int N) {
    __shared__ ulonglong2 s_xy[TS / 2];
    __shared__ ulonglong2 s_zw[TS / 2];
    __shared__ u64        s_lq[TS / 2];
    const int b = blockIdx.y, base = b * N;
    const int t = threadIdx.x, warp = t >> 5, lane = t & 31;
    const int r0 = blockIdx.x * RPB + warp * 4;
    const int c0 = blockIdx.z * (N / CS), c1 = c0 + N / CS;

    u64 rx[4], ry[4], rz[4], rw[4], wa[4], cs[4];
    float lgL[4];
    u64 wm;
    {
        float4 A[4];
#pragma unroll
        for (int r = 0; r < 4; r++) A[r] = g_p1[base + r0 + r];
#pragma unroll
        for (int r = 0; r < 4; r++) {
            rx[r] = pk2(-2.0f * A[r].x, -2.0f * A[r].x);
            ry[r] = pk2(-2.0f * A[r].y, -2.0f * A[r].y);
            rz[r] = pk2(-2.0f * A[r].z, -2.0f * A[r].z);
            rw[r] = pk2(A[r].w, A[r].w);
            lgL[r] = g_lgL[base + r0 + r];
            wa[r] = 0ull; cs[r] = 0ull;
        }
        float wlx = fminf(fminf(A[0].x, A[1].x), fminf(A[2].x, A[3].x));
        float whx = fmaxf(fmaxf(A[0].x, A[1].x), fmaxf(A[2].x, A[3].x));
        float wly = fminf(fminf(A[0].y, A[1].y), fminf(A[2].y, A[3].y));
        float why = fmaxf(fmaxf(A[0].y, A[1].y), fmaxf(A[2].y, A[3].y));
        float wlz = fminf(fminf(A[0].z, A[1].z), fminf(A[2].z, A[3].z));
        float whz = fmaxf(fmaxf(A[0].z, A[1].z), fmaxf(A[2].z, A[3].z));
        bool k0 = chunk_skip(g_cb[1], b * 64 + lane,      wlx, wly, wlz, whx, why, whz, cut2);
        bool k1 = chunk_skip(g_cb[1], b * 64 + lane + 32, wlx, wly, wlz, whx, why, whz, cut2);
        wm = ((u64)__ballot_sync(0xffffffffu, k1) << 32) |
             (u64)__ballot_sync(0xffffffffu, k0);
    }
    const u64 klg2 = pk2(klg, klg);

    for (int c = c0; c < c1; c += TS) {
        const int tb = c >> 6;
        if (((wm >> tb) & 0xFull) == 0xFull) {
            if (__syncthreads_and(1)) continue;
        } else {
            __syncthreads_and(0);
        }
        {
            int j = base + c + 2 * t;
            float4 q0 = g_p2[j], q1 = g_p2[j + 1];
            ulonglong2 xy; xy.x = pk2(q0.x, q1.x); xy.y = pk2(q0.y, q1.y);
            ulonglong2 zw; zw.x = pk2(q0.z, q1.z); zw.y = pk2(q0.w, q1.w);
            s_xy[t] = xy; s_zw[t] = zw;
            s_lq[t] = pk2(g_lgR[j], g_lgR[j + 1]);
        }
        __syncthreads();
#pragma unroll
        for (int it = 0; it < TS / 64; it++) {
            if ((wm >> (tb + it)) & 1ull) continue;
            int p = it * 32 + lane;
            ulonglong2 xy = s_xy[p];
            ulonglong2 zw = s_zw[p];
            u64 lq2 = s_lq[p];
            u64 d0 = f2fma(rz[0], zw.x, f2fma(ry[0], xy.y, f2fma(rx[0], xy.x, f2add(zw.y, rw[0]))));
            u64 d1 = f2fma(rz[1], zw.x, f2fma(ry[1], xy.y, f2fma(rx[1], xy.x, f2add(zw.y, rw[1]))));
            u64 d2 = f2fma(rz[2], zw.x, f2fma(ry[2], xy.y, f2fma(rx[2], xy.x, f2add(zw.y, rw[2]))));
            u64 d3 = f2fma(rz[3], zw.x, f2fma(ry[3], xy.y, f2fma(rx[3], xy.x, f2add(zw.y, rw[3]))));
            u64 a0 = f2fma(klg2, d0, lq2);
            u64 a1 = f2fma(klg2, d1, lq2);
            u64 a2 = f2fma(klg2, d2, lq2);
            u64 a3 = f2fma(klg2, d3, lq2);
            float f0, f1, f2v, f3v, f4, f5, f6, f7;
            upk2(f0, f1, a0); upk2(f2v, f3v, a1); upk2(f4, f5, a2); upk2(f6, f7, a3);
            float m0 = fmaxf(fmaxf(f0, f1), fmaxf(f2v, f3v));
            float m1 = fmaxf(fmaxf(f4, f5), fmaxf(f6, f7));
            if (__all_sync(0xffffffffu, fmaxf(m0, m1) < UF_TH)) continue;
#pragma unroll
            for (int r = 0; r < 4; r++) {
                u64 dd = (r == 0) ? d0 : (r == 1) ? d1 : (r == 2) ? d2 : d3;
                float av0, av1;
                if (r == 0)      { av0 = f0;  av1 = f1; }
                else if (r == 1) { av0 = f2v; av1 = f3v; }
                else if (r == 2) { av0 = f4;  av1 = f5; }
                else             { av0 = f6;  av1 = f7; }
                float dl, dh; upk2(dl, dh, dd);
                float cc0 = fmaxf(dl, 1e-20f), cc1 = fmaxf(dh, 1e-20f);
                float w0 = ex2f(av0), w1 = ex2f(av1);
                float s0 = sqrtf_apx(cc0), s1 = sqrtf_apx(cc1);
                u64 wv = pk2(w0, w1);
                wa[r] = f2add(wa[r], wv);
                cs[r] = f2fma(wv, pk2(s0, s1), cs[r]);
            }
        }
        __syncthreads();
    }

#pragma unroll
    for (int off = 16; off; off >>= 1) {
#pragma unroll
        for (int r = 0; r < 4; r++) {
            wa[r] = f2add(wa[r], __shfl_down_sync(0xffffffffu, wa[r], off));
            cs[r] = f2add(cs[r], __shfl_down_sync(0xffffffffu, cs[r], off));
        }
    }
    if (lane == 0) {
        float cost = 0.0f;
        bool any = false;
#pragma unroll
        for (int r = 0; r < 4; r++) {
            int idx = base + r0 + r;
            float eL = ex2f(lgL[r]);
            float wl, wh; upk2(wl, wh, wa[r]);
            float cl, ch; upk2(cl, ch, cs[r]);
            float w = wl + wh;
            if (w != 0.0f) { atomicAdd(&g_sum[idx], eL * w); any = true; }
            cost = fmaf(eL, cl + ch, cost);
        }
        if (any || cost != 0.0f) atomicAdd(&g_cost, cost);
    }
}

// Epilogues for split sparse passes. grid (B*N/256), block 256.
__global__ void epi1_kernel(int total) {
    int i = blockIdx.x * 256 + threadIdx.x;
    if (i >= total) return;
    g_lgL[i] = lg2f(g_rL[i] / (EMD_EPS + g_sum[i]));
    g_sum[i] = 0.0f;
}
__global__ void epi2_kernel(int total) {
    int i = blockIdx.x * 256 + threadIdx.x;
    if (i >= total) return;
    float rr   = g_rR[i];
    float sumr = rr * g_sum[i];
    float cons = fminf(rr / (sumr + EMD_EPS), 1.0f);
    float nrr  = fmaxf(0.0f, rr - sumr);
    g_lgR[i] = lg2f(cons * rr);
    g_rR[i]  = nrr;
    g_l2R[i] = lg2f(nrr);
    g_sum[i] = 0.0f;
}
__global__ void epi3_kernel(int total) {
    int i = blockIdx.x * 256 + threadIdx.x;
    if (i >= total) return;
    g_rL[i] = fmaxf(0.0f, g_rL[i] - g_sum[i]);   // g_sum already holds eL*wa
    g_sum[i] = 0.0f;
}

// ---------------- DENSE (1024-col smem tiles, inline epilogues) ----------------
template <int MODE, int PRUNE>
__global__ void __launch_bounds__(128, 6) dense12_kernel(float klg, int N) {
    __shared__ ulonglong2 s_xy[TILE / 2];
    __shared__ ulonglong2 s_zf[TILE / 2];
    const int b = blockIdx.y, base = b * N;
    const int t = threadIdx.x, warp = t >> 5, lane = t & 31;
    const int r0 = blockIdx.x * RPB + warp * 4;

    const float4* P    = (MODE == 1) ? g_p1 : g_p2;
    const float4* Q    = (MODE == 1) ? g_p2 : g_p1;
    const float*  FOLD = (MODE == 1) ? g_l2R : g_lgL;

    u64 rx[4], ry[4], rz[4], rw[4], acc[4];
#pragma unroll
    for (int r = 0; r < 4; r++) {
        float4 A = P[base + r0 + r];
        float kx = klg * -2.0f * A.x, ky = klg * -2.0f * A.y, kz = klg * -2.0f * A.z;
        float kw = klg * A.w;
        rx[r] = pk2(kx, kx); ry[r] = pk2(ky, ky); rz[r] = pk2(kz, kz); rw[r] = pk2(kw, kw);
        acc[r] = 0ull;
    }

    for (int c = 0; c < N; c += TILE) {
#pragma unroll
        for (int k = 0; k < TILE / 256; k++) {
            int p = t + k * 128;
            int j = base + c + 2 * p;
            float4 q0 = Q[j], q1 = Q[j + 1];
            float2 fo = *(const float2*)&FOLD[j];
            float f0 = fmaf(klg, q0.w, fo.x);
            float f1 = fmaf(klg, q1.w, fo.y);
            ulonglong2 xy; xy.x = pk2(q0.x, q1.x); xy.y = pk2(q0.y, q1.y);
            ulonglong2 zf; zf.x = pk2(q0.z, q1.z); zf.y = pk2(f0, f1);
            s_xy[p] = xy; s_zf[p] = zf;
        }
        __syncthreads();
#pragma unroll 4
        for (int it = 0; it < TILE / 64; it++) {
            int p = it * 32 + lane;
            ulonglong2 xy = s_xy[p];
            ulonglong2 zf = s_zf[p];
            u64 a0 = f2fma(rz[0], zf.x, f2fma(ry[0], xy.y, f2fma(rx[0], xy.x, f2add(zf.y, rw[0]))));
            u64 a1 = f2fma(rz[1], zf.x, f2fma(ry[1], xy.y, f2fma(rx[1], xy.x, f2add(zf.y, rw[1]))));
            u64 a2 = f2fma(rz[2], zf.x, f2fma(ry[2], xy.y, f2fma(rx[2], xy.x, f2add(zf.y, rw[2]))));
            u64 a3 = f2fma(rz[3], zf.x, f2fma(ry[3], xy.y, f2fma(rx[3], xy.x, f2add(zf.y, rw[3]))));
            float e0, e1, e2, e3, e4, e5, e6, e7;
            upk2(e0, e1, a0); upk2(e2, e3, a1); upk2(e4, e5, a2); upk2(e6, e7, a3);
            if (PRUNE >= 1) {
                float m0 = fmaxf(fmaxf(e0, e1), fmaxf(e2, e3));
                float m1 = fmaxf(fmaxf(e4, e5), fmaxf(e6, e7));
                if (__all_sync(0xffffffffu, fmaxf(m0, m1) < UF_TH)) continue;
            }
            acc[0] = f2add(acc[0], pk2(ex2f(e0), ex2f(e1)));
            acc[1] = f2add(acc[1], pk2(ex2f(e2), ex2f(e3)));
            acc[2] = f2add(acc[2], pk2(ex2f(e4), ex2f(e5)));
            acc[3] = f2add(acc[3], pk2(ex2f(e6), ex2f(e7)));
        }
        __syncthreads();
    }

#pragma unroll
    for (int off = 16; off; off >>= 1) {
#pragma unroll
        for (int r = 0; r < 4; r++)
            acc[r] = f2add(acc[r], __shfl_down_sync(0xffffffffu, acc[r], off));
    }
    if (lane == 0) {
#pragma unroll
        for (int r = 0; r < 4; r++) {
            float lo, hi; upk2(lo, hi, acc[r]);
            epi12(MODE, base + r0 + r, lo + hi);
        }
    }
}

template <int PRUNE>
__global__ void __launch_bounds__(128, 5) dense3_kernel(float klg, int N) {
    __shared__ ulonglong2 s_xy[TILE / 2];
    __shared__ ulonglong2 s_zw[TILE / 2];
    __shared__ u64        s_lq[TILE / 2];
    const int b = blockIdx.y, base = b * N;
    const int t = threadIdx.x, warp = t >> 5, lane = t & 31;
    const int r0 = blockIdx.x * RPB + warp * 4;

    u64 rx[4], ry[4], rz[4], rw[4], wa[4], cs[4];
    float lgL[4];
#pragma unroll
    for (int r = 0; r < 4; r++) {
        float4 A = g_p1[base + r0 + r];
        rx[r] = pk2(-2.0f * A.x, -2.0f * A.x);
        ry[r] = pk2(-2.0f * A.y, -2.0f * A.y);
        rz[r] = pk2(-2.0f * A.z, -2.0f * A.z);
        rw[r] = pk2(A.w, A.w);
        lgL[r] = g_lgL[base + r0 + r];
        wa[r] = 0ull; cs[r] = 0ull;
    }
    const u64 klg2 = pk2(klg, klg);

    for (int c = 0; c < N; c += TILE) {
#pragma unroll
        for (int k = 0; k < TILE / 256; k++) {
            int p = t + k * 128;
            int j = base + c + 2 * p;
            float4 q0 = g_p2[j], q1 = g_p2[j + 1];
            ulonglong2 xy; xy.x = pk2(q0.x, q1.x); xy.y = pk2(q0.y, q1.y);
            ulonglong2 zw; zw.x = pk2(q0.z, q1.z); zw.y = pk2(q0.w, q1.w);
            s_xy[p] = xy; s_zw[p] = zw;
            s_lq[p] = pk2(g_lgR[j], g_lgR[j + 1]);
        }
        __syncthreads();
#pragma unroll 4
        for (int it = 0; it < TILE / 64; it++) {
            int p = it * 32 + lane;
            ulonglong2 xy = s_xy[p];
            ulonglong2 zw = s_zw[p];
            u64 lq2 = s_lq[p];
            u64 d0 = f2fma(rz[0], zw.x, f2fma(ry[0], xy.y, f2fma(rx[0], xy.x, f2add(zw.y, rw[0]))));
            u64 d1 = f2fma(rz[1], zw.x, f2fma(ry[1], xy.y, f2fma(rx[1], xy.x, f2add(zw.y, rw[1]))));
            u64 d2 = f2fma(rz[2], zw.x, f2fma(ry[2], xy.y, f2fma(rx[2], xy.x, f2add(zw.y, rw[2]))));
            u64 d3 = f2fma(rz[3], zw.x, f2fma(ry[3], xy.y, f2fma(rx[3], xy.x, f2add(zw.y, rw[3]))));
            u64 a0 = f2fma(klg2, d0, lq2);
            u64 a1 = f2fma(klg2, d1, lq2);
            u64 a2 = f2fma(klg2, d2, lq2);
            u64 a3 = f2fma(klg2, d3, lq2);
            float f0, f1, f2v, f3v, f4, f5, f6, f7;
            upk2(f0, f1, a0); upk2(f2v, f3v, a1); upk2(f4, f5, a2); upk2(f6, f7, a3);
            if (PRUNE >= 1) {
                float m0 = fmaxf(fmaxf(f0, f1), fmaxf(f2v, f3v));
                float m1 = fmaxf(fmaxf(f4, f5), fmaxf(f6, f7));
                if (__all_sync(0xffffffffu, fmaxf(m0, m1) < UF_TH)) continue;
            }
#pragma unroll
            for (int r = 0; r < 4; r++) {
                u64 dd = (r == 0) ? d0 : (r == 1) ? d1 : (r == 2) ? d2 : d3;
                float av0, av1;
                if (r == 0)      { av0 = f0;  av1 = f1; }
                else if (r == 1) { av0 = f2v; av1 = f3v; }
                else if (r == 2) { av0 = f4;  av1 = f5; }
                else             { av0 = f6;  av1 = f7; }
                float dl, dh; upk2(dl, dh, dd);
                float c0 = fmaxf(dl, 1e-20f), c1 = fmaxf(dh, 1e-20f);
                float w0 = ex2f(av0), w1 = ex2f(av1);
                float s0 = sqrtf_apx(c0), s1 = sqrtf_apx(c1);
                u64 wv = pk2(w0, w1);
                wa[r] = f2add(wa[r], wv);
                cs[r] = f2fma(wv, pk2(s0, s1), cs[r]);
            }
        }
        __syncthreads();
    }

#pragma unroll
    for (int off = 16; off; off >>= 1) {
#pragma unroll
        for (int r = 0; r < 4; r++) {
            wa[r] = f2add(wa[r], __shfl_down_sync(0xffffffffu, wa[r], off));
            cs[r] = f2add(cs[r], __shfl_down_sync(0xffffffffu, cs[r], off));
        }
    }
    if (lane == 0) {
        float cost = 0.0f;
#pragma unroll
        for (int r = 0; r < 4; r++) {
            int idx = base + r0 + r;
            float eL = ex2f(lgL[r]);
            float wl, wh; upk2(wl, wh, wa[r]);
            float cl, ch; upk2(cl, ch, cs[r]);
            g_rL[idx] = fmaxf(0.0f, g_rL[idx] - eL * (wl + wh));
            cost = fmaf(eL, cl + ch, cost);
        }
        atomicAdd(&g_cost, cost);
    }
}

// ---------------- level == 0 sweep (exact) ----------------
__global__ void level0_prep(int N) {
    __shared__ float red[256];
    __shared__ float Tv, Uv;
    const int b = blockIdx.x, base = b * N, t = threadIdx.x;
    float ts = 0.0f, us = 0.0f;
    for (int i = t; i < N; i += 256) { ts += g_rR[base + i]; us += g_rL[base + i]; }
    red[t] = ts; __syncthreads();
    for (int o = 128; o; o >>= 1) { if (t < o) red[t] += red[t + o]; __syncthreads(); }
    if (t == 0) Tv = red[0];
    __syncthreads();
    red[t] = us; __syncthreads();
    for (int o = 128; o; o >>= 1) { if (t < o) red[t] += red[t + o]; __syncthreads(); }
    if (t == 0) Uv = red[0];
    __syncthreads();
    float scale = 1.0f / (EMD_EPS + Tv);
    float S = Uv * scale;
    for (int i = t; i < N; i += 256) {
        g_lgL[base + i] = g_rL[base + i] * scale;     // raw ratioL
        float rr   = g_rR[base + i];
        float sumr = rr * S;
        float cons = fminf(rr / (sumr + EMD_EPS), 1.0f);
        g_lgR[base + i] = cons * rr;                  // raw ratioR
    }
}

__global__ void __launch_bounds__(128, 6) level0_cost(int N) {
    __shared__ ulonglong2 s_xy[TILE / 2];
    __shared__ ulonglong2 s_zw[TILE / 2];
    __shared__ u64        s_rr[TILE / 2];
    const int b = blockIdx.y, base = b * N;
    const int t = threadIdx.x, warp = t >> 5, lane = t & 31;
    const int r0 = blockIdx.x * RPB + warp * 4;

    u64 rx[4], ry[4], rz[4], rw[4], cs[4];
    float rl[4];
#pragma unroll
    for (int r = 0; r < 4; r++) {
        float4 A = g_p1[base + r0 + r];
        rx[r] = pk2(-2.0f * A.x, -2.0f * A.x);
        ry[r] = pk2(-2.0f * A.y, -2.0f * A.y);
        rz[r] = pk2(-2.0f * A.z, -2.0f * A.z);
        rw[r] = pk2(A.w, A.w);
        rl[r] = g_lgL[base + r0 + r];
        cs[r] = 0ull;
    }

    for (int c = 0; c < N; c += TILE) {
#pragma unroll
        for (int k = 0; k < TILE / 256; k++) {
            int p = t + k * 128;
            int j = base + c + 2 * p;
            float4 q0 = g_p2[j], q1 = g_p2[j + 1];
            ulonglong2 xy; xy.x = pk2(q0.x, q1.x); xy.y = pk2(q0.y, q1.y);
            ulonglong2 zw; zw.x = pk2(q0.z, q1.z); zw.y = pk2(q0.w, q1.w);
            s_xy[p] = xy; s_zw[p] = zw;
            s_rr[p] = pk2(g_lgR[j], g_lgR[j + 1]);
        }
        __syncthreads();
#pragma unroll 4
        for (int it = 0; it < TILE / 64; it++) {
            int p = it * 32 + lane;
            ulonglong2 xy = s_xy[p];
            ulonglong2 zw = s_zw[p];
            u64 rr2 = s_rr[p];
#pragma unroll
            for (int r = 0; r < 4; r++) {
                u64 dd = f2fma(rz[r], zw.x, f2fma(ry[r], xy.y, f2fma(rx[r], xy.x, f2add(zw.y, rw[r]))));
                float dl, dh; upk2(dl, dh, dd);
                float s0 = sqrtf_apx(fmaxf(dl, 1e-20f));
                float s1 = sqrtf_apx(fmaxf(dh, 1e-20f));
                cs[r] = f2fma(rr2, pk2(s0, s1), cs[r]);
            }
        }
        __syncthreads();
    }

#pragma unroll
    for (int off = 16; off; off >>= 1) {
#pragma unroll
        for (int r = 0; r < 4; r++)
            cs[r] = f2add(cs[r], __shfl_down_sync(0xffffffffu, cs[r], off));
    }
    if (lane == 0) {
        float cost = 0.0f;
#pragma unroll
        for (int r = 0; r < 4; r++) {
            float cl, ch; upk2(cl, ch, cs[r]);
            cost = fmaf(rl[r], cl + ch, cost);
        }
        atomicAdd(&g_cost, cost);
    }
}

__global__ void final_kernel(float* out, float inv) {
    out[0] = g_cost * inv;
}

extern "C" void kernel_launch(void* const* d_in, const int* in_sizes, int n_in,
                              void* d_out, int out_size) {
    const float* x1 = (const float*)d_in[0];
    const float* x2 = (const float*)d_in[1];
    const int B = NB;
    const int N = in_sizes[0] / (3 * B);   // 4096
    const int n = N, m = N;

    float multiL, multiR;
    if (n >= m) { multiL = 1.0f; multiR = (float)(n / m); }
    else        { multiL = (float)(m / n); multiR = 1.0f; }

    sort_kernel<<<dim3(B, 2), 512>>>(x1, x2, multiL, multiR, N);
    bbox_kernel<<<dim3(B, 2), 512>>>(N);

    dim3 gridD(N / RPB, B);
    dim3 gridS(N / RPB, B, CS);
    const int total = B * N;
    const int eb = (total + 255) / 256;
    const float LOG2E = 1.4426950408889634f;
    for (int s = 0; s < 9; s++) {
        float level = -ldexpf(1.0f, 2 * (7 - s));   // -4^(7-s); s=8 -> -0.25
        float klg = level * LOG2E;
        float cutA = 130.0f / (-klg);   // P1/P3: col fold <= 0
        float cutB = 160.0f / (-klg);   // P2: col fold lgL <= ~30
        if (s <= 4) {            // sparse: column-split sum + epilogue
            sparse12_sum<1><<<gridS, 128>>>(klg, cutA, N);
            epi1_kernel<<<eb, 256>>>(total);
            sparse12_sum<2><<<gridS, 128>>>(klg, cutB, N);
            epi2_kernel<<<eb, 256>>>(total);
            sparse3_sum<<<gridS, 128>>>(klg, cutA, N);
            epi3_kernel<<<eb, 256>>>(total);
        } else if (s == 5) {     // dense + arg-vote
            dense12_kernel<1, 1><<<gridD, 128>>>(klg, N);
            dense12_kernel<2, 1><<<gridD, 128>>>(klg, N);
            dense3_kernel<1><<<gridD, 128>>>(klg, N);
        } else {                 // fully dense
            dense12_kernel<1, 0><<<gridD, 128>>>(klg, N);
            dense12_kernel<2, 0><<<gridD, 128>>>(klg, N);
            dense3_kernel<0><<<gridD, 128>>>(klg, N);
        }
    }
    level0_prep<<<B, 256>>>(N);
    level0_cost<<<gridD, 128>>>(N);

    float mn = (float)((n < m ? n : m) * B);
    final_kernel<<<1, 1>>>((float*)d_out, 1.0f / mn);
}

// round 9
// speedup vs baseline: 1.0269x; 1.0269x over previous
#include <cuda_runtime.h>
#include <math.h>

// EMD approxmatch (Fan et al.) on GB300 — round 9.
// Unified pruned pass kernels for ALL sweeps: spatial bbox masks + magnitude
// (fold-max) masks + dead-row warp early-outs + arg-vote. Packed f32x2 math.
// Exact level-0 sweep with raw-zero masks. B=4, N=4096, 32 launches.

#define EMD_EPS 1e-9f
#define NB 4
#define MAXBN (NB * 4096)
#define TS 256         // tile (cols per smem fill)
#define RPB 16         // rows per block: 4 warps x 4 rows
#define UF_TH (-125.0f)
#define NEG_INF (-__int_as_float(0x7f800000))

typedef unsigned long long u64;

__device__ float4 g_p1[MAXBN];     // sorted (x,y,z,|p|^2) xyz1
__device__ float4 g_p2[MAXBN];     // sorted (x,y,z,|p|^2) xyz2
__device__ float  g_rL[MAXBN];
__device__ float  g_rR[MAXBN];
__device__ float  g_l2R[MAXBN];    // log2(remainR)
__device__ float  g_lgL[MAXBN];    // log2(ratioL)   (raw ratioL during level-0)
__device__ float  g_lgR[MAXBN];    // log2(ratioR)   (raw ratioR during level-0)
__device__ float  g_rmL[MAXBN/4];  // per-4-row max of lgL (x1)      [P1 epi -> P2 mask]
__device__ float  g_rmR2[MAXBN/4]; // per-4-row max of l2R (x2)      [sort/P2 epi -> P1 mask]
__device__ float  g_rmR3[MAXBN/4]; // per-4-row max of lgR (x2)      [P2 epi -> P3 mask; raw in level0]
__device__ float  g_cost;
__device__ float4 g_cb[2][NB * 64 * 2];  // 64-pt chunk bboxes

__device__ __forceinline__ float ex2f(float x) {
    float y; asm("ex2.approx.ftz.f32 %0, %1;" : "=f"(y) : "f"(x)); return y;
}
__device__ __forceinline__ float lg2f(float x) {
    float y; asm("lg2.approx.ftz.f32 %0, %1;" : "=f"(y) : "f"(x)); return y;
}
__device__ __forceinline__ float sqrtf_apx(float x) {
    float y; asm("sqrt.approx.ftz.f32 %0, %1;" : "=f"(y) : "f"(x)); return y;
}
__device__ __forceinline__ u64 pk2(float a, float b) {
    u64 r; asm("mov.b64 %0, {%1, %2};" : "=l"(r) : "f"(a), "f"(b)); return r;
}
__device__ __forceinline__ void upk2(float& a, float& b, u64 v) {
    asm("mov.b64 {%0, %1}, %2;" : "=f"(a), "=f"(b) : "l"(v));
}
__device__ __forceinline__ u64 f2fma(u64 a, u64 b, u64 c) {
    u64 d; asm("fma.rn.f32x2 %0, %1, %2, %3;" : "=l"(d) : "l"(a), "l"(b), "l"(c)); return d;
}
__device__ __forceinline__ u64 f2add(u64 a, u64 b) {
    u64 d; asm("add.rn.f32x2 %0, %1, %2;" : "=l"(d) : "l"(a), "l"(b)); return d;
}

__device__ __forceinline__ unsigned mort1(unsigned v) {
    return (v & 1u) | ((v & 2u) << 2) | ((v & 4u) << 4);
}

// squared gap between warp bbox and chunk bbox
__device__ __forceinline__ float box_gap2(const float4* CB, int ci,
                                          float wlx, float wly, float wlz,
                                          float whx, float why, float whz) {
    float4 clo = __ldg(&CB[ci * 2]);
    float4 chi = __ldg(&CB[ci * 2 + 1]);
    float gx = fmaxf(0.0f, fmaxf(clo.x - whx, wlx - chi.x));
    float gy = fmaxf(0.0f, fmaxf(clo.y - why, wly - chi.y));
    float gz = fmaxf(0.0f, fmaxf(clo.z - whz, wlz - chi.z));
    return fmaf(gx, gx, fmaf(gy, gy, gz * gz));
}

// Counting sort by Morton cell id (8^3 cells over [-4,4]^3). grid (B,2), block 512.
__global__ void sort_kernel(const float* __restrict__ x1, const float* __restrict__ x2,
                            float multiL, float multiR, int N) {
    __shared__ unsigned hist[512];
    __shared__ unsigned scan[512];
    __shared__ unsigned offs[512];
    const int b = blockIdx.x, side = blockIdx.y, t = threadIdx.x;
    const float* px = (side ? x2 : x1) + (size_t)b * 3 * N;
    hist[t] = 0;
    __syncthreads();
    for (int i = t; i < N; i += 512) {
        float a = px[i], c = px[i + N], d = px[i + 2 * N];
        unsigned cx = (unsigned)min(7, max(0, (int)floorf(a + 4.0f)));
        unsigned cy = (unsigned)min(7, max(0, (int)floorf(c + 4.0f)));
        unsigned cz = (unsigned)min(7, max(0, (int)floorf(d + 4.0f)));
        unsigned cell = mort1(cx) | (mort1(cy) << 1) | (mort1(cz) << 2);
        atomicAdd(&hist[cell], 1u);
    }
    __syncthreads();
    scan[t] = hist[t];
    __syncthreads();
    for (int o = 1; o < 512; o <<= 1) {
        unsigned add = (t >= o) ? scan[t - o] : 0u;
        __syncthreads();
        scan[t] += add;
        __syncthreads();
    }
    offs[t] = scan[t] - hist[t];
    __syncthreads();
    for (int i = t; i < N; i += 512) {
        float a = px[i], c = px[i + N], d = px[i + 2 * N];
        unsigned cx = (unsigned)min(7, max(0, (int)floorf(a + 4.0f)));
        unsigned cy = (unsigned)min(7, max(0, (int)floorf(c + 4.0f)));
        unsigned cz = (unsigned)min(7, max(0, (int)floorf(d + 4.0f)));
        unsigned cell = mort1(cx) | (mort1(cy) << 1) | (mort1(cz) << 2);
        unsigned pos = atomicAdd(&offs[cell], 1u);
        int idx = b * N + (int)pos;
        float4 v = make_float4(a, c, d, a * a + c * c + d * d);
        if (side == 0) { g_p1[idx] = v; g_rL[idx] = multiL; }
        else           { g_p2[idx] = v; g_rR[idx] = multiR; g_l2R[idx] = lg2f(multiR); }
    }
    if (side == 1) {
        for (int i = t; i < N / 4; i += 512) g_rmR2[b * (N / 4) + i] = lg2f(multiR);
    }
    if (b == 0 && side == 0 && t == 0) g_cost = 0.0f;
}

// Chunk (64-pt) bboxes. grid (B,2), block 512.
__global__ void bbox_kernel(int N) {
    const int b = blockIdx.x, side = blockIdx.y, t = threadIdx.x;
    const int warp = t >> 5, lane = t & 31;
    const float4* P = side ? g_p2 : g_p1;
    float4* CB = g_cb[side];
    for (int c = warp; c < 64; c += 16) {
        int j = b * N + c * 64 + lane;
        float4 p0 = P[j], p1 = P[j + 32];
        float lx = fminf(p0.x, p1.x), hx = fmaxf(p0.x, p1.x);
        float ly = fminf(p0.y, p1.y), hy = fmaxf(p0.y, p1.y);
        float lz = fminf(p0.z, p1.z), hz = fmaxf(p0.z, p1.z);
#pragma unroll
        for (int o = 16; o; o >>= 1) {
            lx = fminf(lx, __shfl_xor_sync(0xffffffffu, lx, o));
            hx = fmaxf(hx, __shfl_xor_sync(0xffffffffu, hx, o));
            ly = fminf(ly, __shfl_xor_sync(0xffffffffu, ly, o));
            hy = fmaxf(hy, __shfl_xor_sync(0xffffffffu, hy, o));
            lz = fminf(lz, __shfl_xor_sync(0xffffffffu, lz, o));
            hz = fmaxf(hz, __shfl_xor_sync(0xffffffffu, hz, o));
        }
        if (lane == 0) {
            CB[(b * 64 + c) * 2]     = make_float4(lx, ly, lz, 0.0f);
            CB[(b * 64 + c) * 2 + 1] = make_float4(hx, hy, hz, 0.0f);
        }
    }
}

// ---------------- unified P1/P2 kernel (all sweeps) ----------------
// MODE 1: rows=x1 (weight rL), cols=x2, fold=g_l2R, cm=g_rmR2; writes lgL + rmL.
// MODE 2: rows=x2 (weight rR), cols=x1, fold=g_lgL, cm=g_rmL; writes lgR,rR,l2R + rmR2,rmR3.
template <int MODE>
__global__ void __launch_bounds__(128, 6) pass12_kernel(float klg, int N) {
    __shared__ ulonglong2 s_xy[TS / 2];
    __shared__ ulonglong2 s_zf[TS / 2];
    __shared__ float s_cm[64];
    __shared__ unsigned s_bm[4][2];
    const int b = blockIdx.y, base = b * N;
    const int t = threadIdx.x, warp = t >> 5, lane = t & 31;
    const int r0 = blockIdx.x * RPB + warp * 4;

    const float4* P    = (MODE == 1) ? g_p1 : g_p2;
    const float4* Q    = (MODE == 1) ? g_p2 : g_p1;
    const float4* CB   = (MODE == 1) ? g_cb[1] : g_cb[0];
    const float*  FOLD = (MODE == 1) ? g_l2R : g_lgL;
    const float*  RM   = (MODE == 1) ? g_rmR2 : g_rmL;

    // block chunk fold-max
    if (t < 64) {
        float m = NEG_INF;
#pragma unroll
        for (int k = 0; k < 16; k++) m = fmaxf(m, RM[b * (N / 4) + t * 16 + k]);
        s_cm[t] = m;
    }

    u64 rx[4], ry[4], rz[4], rw[4], acc[4];
    float4 A[4];
    float rowv[4];
#pragma unroll
    for (int r = 0; r < 4; r++) {
        A[r] = P[base + r0 + r];
        rowv[r] = (MODE == 1) ? g_rL[base + r0 + r] : g_rR[base + r0 + r];
    }
#pragma unroll
    for (int r = 0; r < 4; r++) {
        float kx = klg * -2.0f * A[r].x, ky = klg * -2.0f * A[r].y, kz = klg * -2.0f * A[r].z;
        float kw = klg * A[r].w;
        rx[r] = pk2(kx, kx); ry[r] = pk2(ky, ky); rz[r] = pk2(kz, kz); rw[r] = pk2(kw, kw);
        acc[r] = 0ull;
    }
    bool rowsDead = (fmaxf(fmaxf(rowv[0], rowv[1]), fmaxf(rowv[2], rowv[3])) == 0.0f);
    __syncthreads();   // s_cm ready

    u64 wm;
    if (rowsDead) {
        __ballot_sync(0xffffffffu, 1);   // keep warp converged (no-op)
        wm = ~0ull;
        if (lane == 0) { s_bm[warp][0] = 0xffffffffu; s_bm[warp][1] = 0xffffffffu; }
    } else {
        float wlx = fminf(fminf(A[0].x, A[1].x), fminf(A[2].x, A[3].x));
        float whx = fmaxf(fmaxf(A[0].x, A[1].x), fmaxf(A[2].x, A[3].x));
        float wly = fminf(fminf(A[0].y, A[1].y), fminf(A[2].y, A[3].y));
        float why = fmaxf(fmaxf(A[0].y, A[1].y), fmaxf(A[2].y, A[3].y));
        float wlz = fminf(fminf(A[0].z, A[1].z), fminf(A[2].z, A[3].z));
        float whz = fmaxf(fmaxf(A[0].z, A[1].z), fmaxf(A[2].z, A[3].z));
        float g0 = box_gap2(CB, b * 64 + lane,      wlx, wly, wlz, whx, why, whz);
        float g1 = box_gap2(CB, b * 64 + lane + 32, wlx, wly, wlz, whx, why, whz);
        bool k0 = fmaf(klg, g0, s_cm[lane])      < UF_TH;
        bool k1 = fmaf(klg, g1, s_cm[lane + 32]) < UF_TH;
        unsigned lo = __ballot_sync(0xffffffffu, k0);
        unsigned hi = __ballot_sync(0xffffffffu, k1);
        wm = ((u64)hi << 32) | lo;
        if (lane == 0) { s_bm[warp][0] = lo; s_bm[warp][1] = hi; }
    }
    __syncthreads();
    u64 bm = (((u64)(s_bm[0][1] & s_bm[1][1] & s_bm[2][1] & s_bm[3][1])) << 32) |
             (u64)(s_bm[0][0] & s_bm[1][0] & s_bm[2][0] & s_bm[3][0]);

    for (int c = 0; c < N; c += TS) {
        const int tb = c >> 6;   // 4 chunks per tile
        if (((bm >> tb) & 0xFull) == 0xFull) continue;
        {
            int j = base + c + 2 * t;
            float4 q0 = Q[j], q1 = Q[j + 1];
            float2 fo = *(const float2*)&FOLD[j];
            float f0 = fmaf(klg, q0.w, fo.x);
            float f1 = fmaf(klg, q1.w, fo.y);
            ulonglong2 xy; xy.x = pk2(q0.x, q1.x); xy.y = pk2(q0.y, q1.y);
            ulonglong2 zf; zf.x = pk2(q0.z, q1.z); zf.y = pk2(f0, f1);
            s_xy[t] = xy; s_zf[t] = zf;
        }
        __syncthreads();
#pragma unroll
        for (int it = 0; it < TS / 64; it++) {
            if ((wm >> (tb + it)) & 1ull) continue;
            int p = it * 32 + lane;
            ulonglong2 xy = s_xy[p];
            ulonglong2 zf = s_zf[p];
            u64 a0 = f2fma(rz[0], zf.x, f2fma(ry[0], xy.y, f2fma(rx[0], xy.x, f2add(zf.y, rw[0]))));
            u64 a1 = f2fma(rz[1], zf.x, f2fma(ry[1], xy.y, f2fma(rx[1], xy.x, f2add(zf.y, rw[1]))));
            u64 a2 = f2fma(rz[2], zf.x, f2fma(ry[2], xy.y, f2fma(rx[2], xy.x, f2add(zf.y, rw[2]))));
            u64 a3 = f2fma(rz[3], zf.x, f2fma(ry[3], xy.y, f2fma(rx[3], xy.x, f2add(zf.y, rw[3]))));
            float e0, e1, e2, e3, e4, e5, e6, e7;
            upk2(e0, e1, a0); upk2(e2, e3, a1); upk2(e4, e5, a2); upk2(e6, e7, a3);
            float m0 = fmaxf(fmaxf(e0, e1), fmaxf(e2, e3));
            float m1 = fmaxf(fmaxf(e4, e5), fmaxf(e6, e7));
            if (__all_sync(0xffffffffu, fmaxf(m0, m1) < UF_TH)) continue;
            acc[0] = f2add(acc[0], pk2(ex2f(e0), ex2f(e1)));
            acc[1] = f2add(acc[1], pk2(ex2f(e2), ex2f(e3)));
            acc[2] = f2add(acc[2], pk2(ex2f(e4), ex2f(e5)));
            acc[3] = f2add(acc[3], pk2(ex2f(e6), ex2f(e7)));
        }
        __syncthreads();
    }

#pragma unroll
    for (int off = 16; off; off >>= 1) {
#pragma unroll
        for (int r = 0; r < 4; r++)
            acc[r] = f2add(acc[r], __shfl_down_sync(0xffffffffu, acc[r], off));
    }
    if (lane == 0) {
        int idx4 = (base + r0) >> 2;
        if (MODE == 1) {
            float mx = NEG_INF;
#pragma unroll
            for (int r = 0; r < 4; r++) {
                float lo, hi; upk2(lo, hi, acc[r]);
                float lg = lg2f(rowv[r] / (EMD_EPS + (lo + hi)));
                g_lgL[base + r0 + r] = lg;
                mx = fmaxf(mx, lg);
            }
            g_rmL[idx4] = mx;
        } else {
            float mx2 = NEG_INF, mx3 = NEG_INF;
#pragma unroll
            for (int r = 0; r < 4; r++) {
                float lo, hi; upk2(lo, hi, acc[r]);
                float a = lo + hi;
                float rr   = rowv[r];
                float sumr = rr * a;
                float cons = fminf(rr / (sumr + EMD_EPS), 1.0f);
                float nrr  = fmaxf(0.0f, rr - sumr);
                float lgr  = lg2f(cons * rr);
                float l2r  = lg2f(nrr);
                g_lgR[base + r0 + r] = lgr;
                g_rR[base + r0 + r]  = nrr;
                g_l2R[base + r0 + r] = l2r;
                mx2 = fmaxf(mx2, l2r);
                mx3 = fmaxf(mx3, lgr);
            }
            g_rmR2[idx4] = mx2;
            g_rmR3[idx4] = mx3;
        }
    }
}

// ---------------- unified P3 kernel (all sweeps) ----------------
__global__ void __launch_bounds__(128, 6) pass3_kernel(float klg, int N) {
    __shared__ ulonglong2 s_xy[TS / 2];
    __shared__ ulonglong2 s_zw[TS / 2];
    __shared__ u64        s_lq[TS / 2];
    __shared__ float s_cm[64];
    __shared__ unsigned s_bm[4][2];
    const int b = blockIdx.y, base = b * N;
    const int t = threadIdx.x, warp = t >> 5, lane = t & 31;
    const int r0 = blockIdx.x * RPB + warp * 4;

    if (t < 64) {
        float m = NEG_INF;
#pragma unroll
        for (int k = 0; k < 16; k++) m = fmaxf(m, g_rmR3[b * (N / 4) + t * 16 + k]);
        s_cm[t] = m;
    }

    u64 rx[4], ry[4], rz[4], rw[4], wa[4], cs[4];
    float lgL[4];
    float4 A[4];
#pragma unroll
    for (int r = 0; r < 4; r++) {
        A[r] = g_p1[base + r0 + r];
        lgL[r] = g_lgL[base + r0 + r];
    }
#pragma unroll
    for (int r = 0; r < 4; r++) {
        rx[r] = pk2(-2.0f * A[r].x, -2.0f * A[r].x);
        ry[r] = pk2(-2.0f * A[r].y, -2.0f * A[r].y);
        rz[r] = pk2(-2.0f * A[r].z, -2.0f * A[r].z);
        rw[r] = pk2(A[r].w, A[r].w);
        wa[r] = 0ull; cs[r] = 0ull;
    }
    float wmaxL = fmaxf(fmaxf(lgL[0], lgL[1]), fmaxf(lgL[2], lgL[3]));
    bool rowsDead = (wmaxL < -126.0f);   // eL == 0 exactly for all rows
    __syncthreads();

    u64 wm;
    if (rowsDead) {
        __ballot_sync(0xffffffffu, 1);
        wm = ~0ull;
        if (lane == 0) { s_bm[warp][0] = 0xffffffffu; s_bm[warp][1] = 0xffffffffu; }
    } else {
        float wlx = fminf(fminf(A[0].x, A[1].x), fminf(A[2].x, A[3].x));
        float whx = fmaxf(fmaxf(A[0].x, A[1].x), fmaxf(A[2].x, A[3].x));
        float wly = fminf(fminf(A[0].y, A[1].y), fminf(A[2].y, A[3].y));
        float why = fmaxf(fmaxf(A[0].y, A[1].y), fmaxf(A[2].y, A[3].y));
        float wlz = fminf(fminf(A[0].z, A[1].z), fminf(A[2].z, A[3].z));
        float whz = fmaxf(fmaxf(A[0].z, A[1].z), fmaxf(A[2].z, A[3].z));
        float g0 = box_gap2(g_cb[1], b * 64 + lane,      wlx, wly, wlz, whx, why, whz);
        float g1 = box_gap2(g_cb[1], b * 64 + lane + 32, wlx, wly, wlz, whx, why, whz);
        bool k0 = fmaf(klg, g0, s_cm[lane]      + wmaxL) < UF_TH;
        bool k1 = fmaf(klg, g1, s_cm[lane + 32] + wmaxL) < UF_TH;
        unsigned lo = __ballot_sync(0xffffffffu, k0);
        unsigned hi = __ballot_sync(0xffffffffu, k1);
        wm = ((u64)hi << 32) | lo;
        if (lane == 0) { s_bm[warp][0] = lo; s_bm[warp][1] = hi; }
    }
    __syncthreads();
    u64 bm = (((u64)(s_bm[0][1] & s_bm[1][1] & s_bm[2][1] & s_bm[3][1])) << 32) |
             (u64)(s_bm[0][0] & s_bm[1][0] & s_bm[2][0] & s_bm[3][0]);
    const u64 klg2 = pk2(klg, klg);

    for (int c = 0; c < N; c += TS) {
        const int tb = c >> 6;
        if (((bm >> tb) & 0xFull) == 0xFull) continue;
        {
            int j = base + c + 2 * t;
            float4 q0 = g_p2[j], q1 = g_p2[j + 1];
            ulonglong2 xy; xy.x = pk2(q0.x, q1.x); xy.y = pk2(q0.y, q1.y);
            ulonglong2 zw; zw.x = pk2(q0.z, q1.z); zw.y = pk2(q0.w, q1.w);
            s_xy[t] = xy; s_zw[t] = zw;
            s_lq[t] = pk2(g_lgR[j], g_lgR[j + 1]);
        }
        __syncthreads();
#pragma unroll
        for (int it = 0; it < TS / 64; it++) {
            if ((wm >> (tb + it)) & 1ull) continue;
            int p = it * 32 + lane;
            ulonglong2 xy = s_xy[p];
            ulonglong2 zw = s_zw[p];
            u64 lq2 = s_lq[p];
            u64 d0 = f2fma(rz[0], zw.x, f2fma(ry[0], xy.y, f2fma(rx[0], xy.x, f2add(zw.y, rw[0]))));
            u64 d1 = f2fma(rz[1], zw.x, f2fma(ry[1], xy.y, f2fma(rx[1], xy.x, f2add(zw.y, rw[1]))));
            u64 d2 = f2fma(rz[2], zw.x, f2fma(ry[2], xy.y, f2fma(rx[2], xy.x, f2add(zw.y, rw[2]))));
            u64 d3 = f2fma(rz[3], zw.x, f2fma(ry[3], xy.y, f2fma(rx[3], xy.x, f2add(zw.y, rw[3]))));
            u64 a0 = f2fma(klg2, d0, lq2);
            u64 a1 = f2fma(klg2, d1, lq2);
            u64 a2 = f2fma(klg2, d2, lq2);
            u64 a3 = f2fma(klg2, d3, lq2);
            float f0, f1, f2v, f3v, f4, f5, f6, f7;
            upk2(f0, f1, a0); upk2(f2v, f3v, a1); upk2(f4, f5, a2); upk2(f6, f7, a3);
            float m0 = fmaxf(fmaxf(f0, f1), fmaxf(f2v, f3v));
            float m1 = fmaxf(fmaxf(f4, f5), fmaxf(f6, f7));
            if (__all_sync(0xffffffffu, fmaxf(m0, m1) < UF_TH)) continue;
#pragma unroll
            for (int r = 0; r < 4; r++) {
                u64 dd = (r == 0) ? d0 : (r == 1) ? d1 : (r == 2) ? d2 : d3;
                float av0, av1;
                if (r == 0)      { av0 = f0;  av1 = f1; }
                else if (r == 1) { av0 = f2v; av1 = f3v; }
                else if (r == 2) { av0 = f4;  av1 = f5; }
                else             { av0 = f6;  av1 = f7; }
                float dl, dh; upk2(dl, dh, dd);
                float c0 = fmaxf(dl, 1e-20f), c1 = fmaxf(dh, 1e-20f);
                float w0 = ex2f(av0), w1 = ex2f(av1);
                float s0 = sqrtf_apx(c0), s1 = sqrtf_apx(c1);
                u64 wv = pk2(w0, w1);
                wa[r] = f2add(wa[r], wv);
                cs[r] = f2fma(wv, pk2(s0, s1), cs[r]);
            }
        }
        __syncthreads();
    }

#pragma unroll
    for (int off = 16; off; off >>= 1) {
#pragma unroll
        for (int r = 0; r < 4; r++) {
            wa[r] = f2add(wa[r], __shfl_down_sync(0xffffffffu, wa[r], off));
            cs[r] = f2add(cs[r], __shfl_down_sync(0xffffffffu, cs[r], off));
        }
    }
    if (lane == 0 && !rowsDead) {
        float cost = 0.0f;
#pragma unroll
        for (int r = 0; r < 4; r++) {
            int idx = base + r0 + r;
            float eL = ex2f(lgL[r]);
            float wl, wh; upk2(wl, wh, wa[r]);
            float cl, ch; upk2(cl, ch, cs[r]);
            g_rL[idx] = fmaxf(0.0f, g_rL[idx] - eL * (wl + wh));
            cost = fmaf(eL, cl + ch, cost);
        }
        atomicAdd(&g_cost, cost);
    }
}

// ---------------- level == 0 sweep (exact) ----------------
__global__ void level0_prep(int N) {
    __shared__ float red[256];
    __shared__ float Tv, Uv;
    const int b = blockIdx.x, base = b * N, t = threadIdx.x;
    float ts = 0.0f, us = 0.0f;
    for (int i = t; i < N; i += 256) { ts += g_rR[base + i]; us += g_rL[base + i]; }
    red[t] = ts; __syncthreads();
    for (int o = 128; o; o >>= 1) { if (t < o) red[t] += red[t + o]; __syncthreads(); }
    if (t == 0) Tv = red[0];
    __syncthreads();
    red[t] = us; __syncthreads();
    for (int o = 128; o; o >>= 1) { if (t < o) red[t] += red[t + o]; __syncthreads(); }
    if (t == 0) Uv = red[0];
    __syncthreads();
    float scale = 1.0f / (EMD_EPS + Tv);
    float S = Uv * scale;
    for (int g = t; g < N / 4; g += 256) {
        float mxR = 0.0f;
#pragma unroll
        for (int k = 0; k < 4; k++) {
            int i = base + g * 4 + k;
            g_lgL[i] = g_rL[i] * scale;                   // raw ratioL
            float rr   = g_rR[i];
            float sumr = rr * S;
            float cons = fminf(rr / (sumr + EMD_EPS), 1.0f);
            float rat  = cons * rr;
            g_lgR[i] = rat;                               // raw ratioR
            mxR = fmaxf(mxR, rat);
        }
        g_rmR3[b * (N / 4) + g] = mxR;                    // raw ratioR 4-max
    }
}

__global__ void __launch_bounds__(128, 6) level0_cost(int N) {
    __shared__ ulonglong2 s_xy[TS / 2];
    __shared__ ulonglong2 s_zw[TS / 2];
    __shared__ u64        s_rr[TS / 2];
    __shared__ float s_cm[64];
    __shared__ unsigned s_bm[4][2];
    const int b = blockIdx.y, base = b * N;
    const int t = threadIdx.x, warp = t >> 5, lane = t & 31;
    const int r0 = blockIdx.x * RPB + warp * 4;

    if (t < 64) {
        float m = 0.0f;
#pragma unroll
        for (int k = 0; k < 16; k++) m = fmaxf(m, g_rmR3[b * (N / 4) + t * 16 + k]);
        s_cm[t] = m;
    }

    u64 rx[4], ry[4], rz[4], rw[4], cs[4];
    float rl[4];
#pragma unroll
    for (int r = 0; r < 4; r++) {
        float4 A = g_p1[base + r0 + r];
        rx[r] = pk2(-2.0f * A.x, -2.0f * A.x);
        ry[r] = pk2(-2.0f * A.y, -2.0f * A.y);
        rz[r] = pk2(-2.0f * A.z, -2.0f * A.z);
        rw[r] = pk2(A.w, A.w);
        rl[r] = g_lgL[base + r0 + r];   // raw ratioL
        cs[r] = 0ull;
    }
    bool rowsDead = (fmaxf(fmaxf(rl[0], rl[1]), fmaxf(rl[2], rl[3])) == 0.0f);
    __syncthreads();

    u64 wm;
    {
        bool k0 = rowsDead || (s_cm[lane]      == 0.0f);
        bool k1 = rowsDead || (s_cm[lane + 32] == 0.0f);
        unsigned lo = __ballot_sync(0xffffffffu, k0);
        unsigned hi = __ballot_sync(0xffffffffu, k1);
        wm = ((u64)hi << 32) | lo;
        if (lane == 0) { s_bm[warp][0] = lo; s_bm[warp][1] = hi; }
    }
    __syncthreads();
    u64 bm = (((u64)(s_bm[0][1] & s_bm[1][1] & s_bm[2][1] & s_bm[3][1])) << 32) |
             (u64)(s_bm[0][0] & s_bm[1][0] & s_bm[2][0] & s_bm[3][0]);

    for (int c = 0; c < N; c += TS) {
        const int tb = c >> 6;
        if (((bm >> tb) & 0xFull) == 0xFull) continue;
        {
            int j = base + c + 2 * t;
            float4 q0 = g_p2[j], q1 = g_p2[j + 1];
            ulonglong2 xy; xy.x = pk2(q0.x, q1.x); xy.y = pk2(q0.y, q1.y);
            ulonglong2 zw; zw.x = pk2(q0.z, q1.z); zw.y = pk2(q0.w, q1.w);
            s_xy[t] = xy; s_zw[t] = zw;
            s_rr[t] = pk2(g_lgR[j], g_lgR[j + 1]);   // raw ratioR
        }
        __syncthreads();
#pragma unroll
        for (int it = 0; it < TS / 64; it++) {
            if ((wm >> (tb + it)) & 1ull) continue;
            int p = it * 32 + lane;
            ulonglong2 xy = s_xy[p];
            ulonglong2 zw = s_zw[p];
            u64 rr2 = s_rr[p];
            if (__all_sync(0xffffffffu, rr2 == 0ull)) continue;
#pragma unroll
            for (int r = 0; r < 4; r++) {
                u64 dd = f2fma(rz[r], zw.x, f2fma(ry[r], xy.y, f2fma(rx[r], xy.x, f2add(zw.y, rw[r]))));
                float dl, dh; upk2(dl, dh, dd);
                float s0 = sqrtf_apx(fmaxf(dl, 1e-20f));
                float s1 = sqrtf_apx(fmaxf(dh, 1e-20f));
                cs[r] = f2fma(rr2, pk2(s0, s1), cs[r]);
            }
        }
        __syncthreads();
    }

#pragma unroll
    for (int off = 16; off; off >>= 1) {
#pragma unroll
        for (int r = 0; r < 4; r++)
            cs[r] = f2add(cs[r], __shfl_down_sync(0xffffffffu, cs[r], off));
    }
    if (lane == 0 && !rowsDead) {
        float cost = 0.0f;
#pragma unroll
        for (int r = 0; r < 4; r++) {
            float cl, ch; upk2(cl, ch, cs[r]);
            cost = fmaf(rl[r], cl + ch, cost);
        }
        atomicAdd(&g_cost, cost);
    }
}

__global__ void final_kernel(float* out, float inv) {
    out[0] = g_cost * inv;
}

extern "C" void kernel_launch(void* const* d_in, const int* in_sizes, int n_in,
                              void* d_out, int out_size) {
    const float* x1 = (const float*)d_in[0];
    const float* x2 = (const float*)d_in[1];
    const int B = NB;
    const int N = in_sizes[0] / (3 * B);   // 4096
    const int n = N, m = N;

    float multiL, multiR;
    if (n >= m) { multiL = 1.0f; multiR = (float)(n / m); }
    else        { multiL = (float)(m / n); multiR = 1.0f; }

    sort_kernel<<<dim3(B, 2), 512>>>(x1, x2, multiL, multiR, N);
    bbox_kernel<<<dim3(B, 2), 512>>>(N);

    dim3 grid(N / RPB, B);
    const float LOG2E = 1.4426950408889634f;
    for (int s = 0; s < 9; s++) {
        float level = -ldexpf(1.0f, 2 * (7 - s));   // -4^(7-s); s=8 -> -0.25
        float klg = level * LOG2E;
        pass12_kernel<1><<<grid, 128>>>(klg, N);
        pass12_kernel<2><<<grid, 128>>>(klg, N);
        pass3_kernel<<<grid, 128>>>(klg, N);
    }
    level0_prep<<<B, 256>>>(N);
    level0_cost<<<grid, 128>>>(N);

    float mn = (float)((n < m ? n : m) * B);
    final_kernel<<<1, 1>>>((float*)d_out, 1.0f / mn);
}